// round 9
// baseline (speedup 1.0000x reference)
#include <cuda_runtime.h>
#include <cuda_fp16.h>
#include <cstdint>

// ============================================================
// SparseModel: 32 MLPs (64 -> 128 -> 128 -> 128 -> 1, swish)
// HMMA fp16 single-pass. 256-thread CTAs, 2 CTAs/SM (smem = 112KB exactly).
// 4 independent 2-warp row-pair pipelines per CTA (64-thread named barriers).
// Biases/Wo read from global (L2-resident). Warp tile 32x64.
// ============================================================

#define THREADS 256
#define TILES_PER_CTA 4     // 2048 CTAs: subnet o = bid&31, g = bid>>5 (64 groups of 512 rows)

// ---- smem layout (exactly 14 x 8192 = 114688 so 2 CTAs fit per SM) ----
static constexpr int SM_ACT = 0;        // act [128 x 128 fp16] swizzled (32768)
static constexpr int SM_W1  = 32768;    // W1  [128n x 64k fp16]  (16384)
static constexpr int SM_WH0 = 49152;    // Wh0 [128n x 128k fp16] (32768)
static constexpr int SM_WH1 = 81920;    // Wh1                    (32768)
static constexpr int SM_TOTAL = 114688;

// ---- helpers ----
__device__ __forceinline__ uint32_t smem_to_u32(const void* p) {
    uint32_t a;
    asm("{ .reg .u64 t; cvta.to.shared.u64 t, %1; cvt.u32.u64 %0, t; }" : "=r"(a) : "l"(p));
    return a;
}
__device__ __forceinline__ uint32_t swz(uint32_t b) { return b ^ ((b >> 3) & 0x70u); }
__device__ __forceinline__ uint32_t toff(int r, int k) {
    return (uint32_t)(((((k >> 6) << 4) + (r >> 3)) << 10) | ((r & 7) << 7) | ((k & 63) << 1));
}

#define LDSM_X4(r, addr) \
    asm volatile("ldmatrix.sync.aligned.m8n8.x4.shared.b16 {%0,%1,%2,%3}, [%4];" \
        : "=r"((r)[0]), "=r"((r)[1]), "=r"((r)[2]), "=r"((r)[3]) : "r"(addr))
#define MMA16816(d, a, b) \
    asm volatile("mma.sync.aligned.m16n8k16.row.col.f32.f16.f16.f32 " \
        "{%0,%1,%2,%3}, {%4,%5,%6,%7}, {%8,%9}, {%0,%1,%2,%3};" \
        : "+f"((d)[0]), "+f"((d)[1]), "+f"((d)[2]), "+f"((d)[3]) \
        : "r"((a)[0]), "r"((a)[1]), "r"((a)[2]), "r"((a)[3]), "r"((b)[0]), "r"((b)[1]))
#define BARP(id) asm volatile("bar.sync %0, 64;" :: "r"(id) : "memory")

__device__ __forceinline__ float swishf(float v) {
    return __fdividef(v, 1.0f + __expf(-v));
}

// warp-32x64 layer mainloop; acc[mt][nt][e]
template <int NCH>
__device__ __forceinline__ void layer_mma(
    float acc[2][8][4], uint32_t actB, uint32_t wB,
    uint32_t aP0, uint32_t aP1, uint32_t aX, int ka,
    uint32_t bRow0, uint32_t bX, int kb4)
{
    #pragma unroll
    for (int c = 0; c < NCH; ++c) {
        const uint32_t kA  = (uint32_t)(c * 16 + ka);
        const uint32_t kxA = ((kA >> 6) << 14) + (((kA & 63) << 1) ^ aX);
        const uint32_t kB  = (uint32_t)(c * 16 + kb4);
        const uint32_t kxB = ((kB >> 6) << 14) + (((kB & 63) << 1) ^ bX);

        uint32_t ah0[4], ah1[4], bf[8][2];
        LDSM_X4(ah0, actB + aP0 + kxA);
        LDSM_X4(ah1, actB + aP1 + kxA);
        #pragma unroll
        for (int np = 0; np < 4; np++) {
            uint32_t q4[4];
            LDSM_X4(q4, wB + bRow0 + ((uint32_t)np << 11) + kxB);
            bf[2*np][0]   = q4[0]; bf[2*np][1]   = q4[1];
            bf[2*np+1][0] = q4[2]; bf[2*np+1][1] = q4[3];
        }
        #pragma unroll
        for (int nt = 0; nt < 8; nt++) {
            MMA16816(acc[0][nt], ah0, bf[nt]);
            MMA16816(acc[1][nt], ah1, bf[nt]);
        }
    }
}

__global__ void __launch_bounds__(THREADS, 2)
mlp_fused_kernel(const float* __restrict__ x,  const float* __restrict__ W1,
                 const float* __restrict__ b1, const float* __restrict__ Wh,
                 const float* __restrict__ bh, const float* __restrict__ Wo,
                 const float* __restrict__ bo, float* __restrict__ out)
{
    extern __shared__ char smc[];
    const uint32_t smb = smem_to_u32(smc);
    const int tid = threadIdx.x;
    const int wid = tid >> 5;
    const int lane = tid & 31;
    const int o = blockIdx.x & 31;       // subnet
    const int g = blockIdx.x >> 5;       // group of 512 rows

    const int rg = wid >> 1;             // row pair (32 rows), 0..3
    const int wn = wid & 1;              // column half (64 cols)
    const int barid = 1 + rg;            // named barriers 1..4, 64 threads each

    // ---- stage weights (fp16, single rounding; float4 global reads) ----
    {
        const float* W1p = W1 + o * 64 * 128;
        for (int idx = tid; idx < 64 * 128 / 4; idx += THREADS) {
            int k = idx >> 5, j = (idx & 31) << 2;    // W1[o][k][j..j+3] -> B[n=j..][k]
            float4 w = reinterpret_cast<const float4*>(W1p)[idx];
            *reinterpret_cast<__half*>(smc + SM_W1 + swz(toff(j + 0, k))) = __float2half_rn(w.x);
            *reinterpret_cast<__half*>(smc + SM_W1 + swz(toff(j + 1, k))) = __float2half_rn(w.y);
            *reinterpret_cast<__half*>(smc + SM_W1 + swz(toff(j + 2, k))) = __float2half_rn(w.z);
            *reinterpret_cast<__half*>(smc + SM_W1 + swz(toff(j + 3, k))) = __float2half_rn(w.w);
        }
        #pragma unroll
        for (int l = 0; l < 2; l++) {
            const float* Wp = Wh + ((size_t)l * 32 + o) * 128 * 128;
            const int base = l ? SM_WH1 : SM_WH0;
            for (int idx = tid; idx < 128 * 128 / 4; idx += THREADS) {
                int k = idx >> 5, j = (idx & 31) << 2;
                float4 w = reinterpret_cast<const float4*>(Wp)[idx];
                *reinterpret_cast<__half*>(smc + base + swz(toff(j + 0, k))) = __float2half_rn(w.x);
                *reinterpret_cast<__half*>(smc + base + swz(toff(j + 1, k))) = __float2half_rn(w.y);
                *reinterpret_cast<__half*>(smc + base + swz(toff(j + 2, k))) = __float2half_rn(w.z);
                *reinterpret_cast<__half*>(smc + base + swz(toff(j + 3, k))) = __float2half_rn(w.w);
            }
        }
    }
    __syncthreads();

    // bias / head-weight pointers (global, L2-resident)
    const float* bias0 = b1 + o * 128;
    const float* bias1 = bh + (size_t)o * 128;
    const float* bias2 = bh + ((size_t)32 + o) * 128;
    const float* wo    = Wo + o * 128;
    const float bo_v   = __ldg(bo + o);

    // ---- ldmatrix lane addressing (warp tile 32 rows x 64 cols) ----
    const int ra0 = rg * 32 + ((lane >> 3) & 1) * 8 + (lane & 7);
    const uint32_t aP0 = (uint32_t)(((ra0 >> 3) << 10) | ((ra0 & 7) << 7));
    const uint32_t aP1 = aP0 + (2u << 10);             // +16 rows
    const uint32_t aX  = (uint32_t)((lane & 7) << 4);
    const int ka = (lane >> 4) * 8;
    const int quad = lane >> 3;
    const int nb   = ((quad >> 1) << 3) + (lane & 7);
    const int kb4  = (quad & 1) << 3;
    const uint32_t bRow0 = (uint32_t)(((wn * 8 + (nb >> 3)) << 10) | ((nb & 7) << 7));
    const uint32_t bX    = (uint32_t)((lane & 7) << 4);

    const uint32_t actB = smb + SM_ACT;
    const int q = lane >> 2;
    // head partial scratch: k>=64 half of this pair's act rows (disjoint from staging area)
    float* pa = reinterpret_cast<float*>(smc + 16384 + rg * 4096);

    for (int t = 0; t < TILES_PER_CTA; t++) {
        const int m0 = (g * TILES_PER_CTA + t) * 128;

        // ---- stage X rows for this pair: [32 rows x 64 k] fp32 -> fp16 (k<64 region) ----
        {
            const int p = wn * 32 + lane;             // 0..63 within pair
            const int r = rg * 32 + (p >> 1);
            const int kbx = (p & 1) << 5;
            const float4* xp = reinterpret_cast<const float4*>(x + (size_t)(m0 + r) * 64 + kbx);
            #pragma unroll
            for (int qq = 0; qq < 8; qq++) {
                float4 v = xp[qq];
                __half2 hh01 = __halves2half2(__float2half_rn(v.x), __float2half_rn(v.y));
                __half2 hh23 = __halves2half2(__float2half_rn(v.z), __float2half_rn(v.w));
                uint32_t off0 = swz(toff(r, kbx + 4 * qq));
                uint32_t off1 = swz(toff(r, kbx + 4 * qq + 2));
                *reinterpret_cast<uint32_t*>(smc + SM_ACT + off0) = *reinterpret_cast<uint32_t*>(&hh01);
                *reinterpret_cast<uint32_t*>(smc + SM_ACT + off1) = *reinterpret_cast<uint32_t*>(&hh23);
            }
        }
        BARP(barid);                 // (1) X visible to pair

        // ---- layers 0 and 1: MMA then in-place epilogue (single buffer) ----
        #pragma unroll
        for (int l = 0; l < 2; l++) {
            float acc[2][8][4];
            #pragma unroll
            for (int mt = 0; mt < 2; mt++)
                #pragma unroll
                for (int nt = 0; nt < 8; nt++)
                    #pragma unroll
                    for (int e = 0; e < 4; e++) acc[mt][nt][e] = 0.0f;

            if (l == 0)
                layer_mma<4>(acc, actB, smb + SM_W1,  aP0, aP1, aX, ka, bRow0, bX, kb4);
            else
                layer_mma<8>(acc, actB, smb + SM_WH0, aP0, aP1, aX, ka, bRow0, bX, kb4);

            BARP(barid);             // pair done reading act before rewriting it
            const float* bias = (l == 0) ? bias0 : bias1;
            #pragma unroll
            for (int mt = 0; mt < 2; mt++) {
                const uint32_t rp0 = (uint32_t)(((rg * 4 + mt * 2) << 10) | (q << 7));
                const uint32_t rp1 = rp0 + (1u << 10);
                #pragma unroll
                for (int nt = 0; nt < 8; nt++) {
                    const int cc = wn * 64 + nt * 8 + (lane & 3) * 2;
                    const float2 bv = *reinterpret_cast<const float2*>(bias + cc);
                    float s0 = swishf(acc[mt][nt][0] + bv.x);
                    float s1 = swishf(acc[mt][nt][1] + bv.y);
                    float s2 = swishf(acc[mt][nt][2] + bv.x);
                    float s3 = swishf(acc[mt][nt][3] + bv.y);
                    __half2 hh01 = __halves2half2(__float2half_rn(s0), __float2half_rn(s1));
                    __half2 hh23 = __halves2half2(__float2half_rn(s2), __float2half_rn(s3));
                    const uint32_t kx = (uint32_t)(((cc >> 6) << 14) +
                                        (((cc & 63) << 1) ^ (q << 4)));
                    *reinterpret_cast<uint32_t*>(smc + SM_ACT + rp0 + kx) = *reinterpret_cast<uint32_t*>(&hh01);
                    *reinterpret_cast<uint32_t*>(smc + SM_ACT + rp1 + kx) = *reinterpret_cast<uint32_t*>(&hh23);
                }
            }
            BARP(barid);             // writes visible before next layer's reads
        }

        // ---- layer 2 + fused scalar head ----
        {
            float acc[2][8][4];
            #pragma unroll
            for (int mt = 0; mt < 2; mt++)
                #pragma unroll
                for (int nt = 0; nt < 8; nt++)
                    #pragma unroll
                    for (int e = 0; e < 4; e++) acc[mt][nt][e] = 0.0f;

            layer_mma<8>(acc, actB, smb + SM_WH1, aP0, aP1, aX, ka, bRow0, bX, kb4);

            float ps[4] = {0.f, 0.f, 0.f, 0.f};
            #pragma unroll
            for (int mt = 0; mt < 2; mt++) {
                #pragma unroll
                for (int nt = 0; nt < 8; nt++) {
                    const int cc = wn * 64 + nt * 8 + (lane & 3) * 2;
                    const float2 bv = *reinterpret_cast<const float2*>(bias2 + cc);
                    const float2 wv = *reinterpret_cast<const float2*>(wo + cc);
                    ps[mt * 2 + 0] += swishf(acc[mt][nt][0] + bv.x) * wv.x
                                    + swishf(acc[mt][nt][1] + bv.y) * wv.y;
                    ps[mt * 2 + 1] += swishf(acc[mt][nt][2] + bv.x) * wv.x
                                    + swishf(acc[mt][nt][3] + bv.y) * wv.y;
                }
            }
            #pragma unroll
            for (int i = 0; i < 4; i++) {
                ps[i] += __shfl_xor_sync(0xffffffffu, ps[i], 1);
                ps[i] += __shfl_xor_sync(0xffffffffu, ps[i], 2);
            }
            BARP(barid);             // pair's L2 reads done -> pa region reusable
            if ((lane & 3) == 0) {
                const int rl = lane >> 2;             // 0..7
                float* sp = pa + wn * 32;
                sp[rl]      = ps[0];
                sp[rl + 8]  = ps[1];
                sp[rl + 16] = ps[2];
                sp[rl + 24] = ps[3];
            }
            BARP(barid);             // pa visible
            if (wn == 0) {
                float v = pa[lane] + pa[32 + lane];
                out[(size_t)(m0 + rg * 32 + lane) * 32 + o] = v + bo_v;
            }
            // next tile's staging writes only the k<64 region (disjoint from pa),
            // and the post-staging barrier orders everything else.
        }
    }
}

extern "C" void kernel_launch(void* const* d_in, const int* in_sizes, int n_in,
                              void* d_out, int out_size) {
    const float* x  = (const float*)d_in[0];
    const float* W1 = (const float*)d_in[1];
    const float* b1 = (const float*)d_in[2];
    const float* Wh = (const float*)d_in[3];
    const float* bh = (const float*)d_in[4];
    const float* Wo = (const float*)d_in[5];
    const float* bo = (const float*)d_in[6];
    float* out = (float*)d_out;

    cudaFuncSetAttribute(mlp_fused_kernel,
                         cudaFuncAttributeMaxDynamicSharedMemorySize, SM_TOTAL);
    mlp_fused_kernel<<<2048, THREADS, SM_TOTAL>>>(x, W1, b1, Wh, bh, Wo, bo, out);
}

// round 10
// speedup vs baseline: 1.4056x; 1.4056x over previous
#include <cuda_runtime.h>
#include <cuda_fp16.h>
#include <cstdint>

// ============================================================
// SparseModel: 32 MLPs (64 -> 128 -> 128 -> 128 -> 1, swish)
// R6 base (fp16 single-pass, 32x32 warp tile, 16 warps, double-buffered act)
// + single-MUFU swish via tanh.approx.f32 (halves MUFU pipe demand).
// ============================================================

#define THREADS 512
#define TILE_M 128
#define GROUPS 32
#define TILES_PER_CTA 8

// ---- smem layout ----
static constexpr int SM_ACT0  = 0;        // act buf0 [128 x 128 fp16] swizzled
static constexpr int SM_ACT1  = 32768;    // act buf1
static constexpr int SM_W1    = 65536;    // W1  [128n x 64k fp16]
static constexpr int SM_WH0   = 81920;    // Wh0 [128n x 128k fp16]
static constexpr int SM_WH1   = 114688;
static constexpr int SM_PART  = 147456;          // 512 floats
static constexpr int SM_BIAS  = SM_PART + 2048;  // 3 x 128 floats
static constexpr int SM_WO    = SM_BIAS + 1536;  // 128 floats
static constexpr int SM_TOTAL = SM_WO + 512;     // 151552

// ---- helpers ----
__device__ __forceinline__ uint32_t smem_to_u32(const void* p) {
    uint32_t a;
    asm("{ .reg .u64 t; cvta.to.shared.u64 t, %1; cvt.u32.u64 %0, t; }" : "=r"(a) : "l"(p));
    return a;
}
__device__ __forceinline__ uint32_t swz(uint32_t b) { return b ^ ((b >> 3) & 0x70u); }
__device__ __forceinline__ uint32_t toff(int r, int k) {
    return (uint32_t)(((((k >> 6) << 4) + (r >> 3)) << 10) | ((r & 7) << 7) | ((k & 63) << 1));
}

#define LDSM_X4(r, addr) \
    asm volatile("ldmatrix.sync.aligned.m8n8.x4.shared.b16 {%0,%1,%2,%3}, [%4];" \
        : "=r"((r)[0]), "=r"((r)[1]), "=r"((r)[2]), "=r"((r)[3]) : "r"(addr))
#define MMA16816(d, a, b) \
    asm volatile("mma.sync.aligned.m16n8k16.row.col.f32.f16.f16.f32 " \
        "{%0,%1,%2,%3}, {%4,%5,%6,%7}, {%8,%9}, {%0,%1,%2,%3};" \
        : "+f"((d)[0]), "+f"((d)[1]), "+f"((d)[2]), "+f"((d)[3]) \
        : "r"((a)[0]), "r"((a)[1]), "r"((a)[2]), "r"((a)[3]), "r"((b)[0]), "r"((b)[1]))
#define BARG(id) asm volatile("bar.sync %0, 128;" :: "r"(id) : "memory")

// swish via tanh.approx: sigmoid(v) = 0.5*tanh(0.5v) + 0.5  -> 1 MUFU total
__device__ __forceinline__ float swishf(float v) {
    float t;
    const float h = 0.5f * v;
    asm("tanh.approx.f32 %0, %1;" : "=f"(t) : "f"(h));
    return fmaf(h, t, h);
}

// fully-unrolled layer mainloop; acc[mt][nt][e]
template <int NCH>
__device__ __forceinline__ void layer_mma(
    float acc[2][4][4], uint32_t actB, uint32_t wB,
    uint32_t aP0, uint32_t aP1, uint32_t aX, int ka,
    uint32_t bRow0, uint32_t bX, int kb4)
{
    #pragma unroll
    for (int c = 0; c < NCH; ++c) {
        const uint32_t kA  = (uint32_t)(c * 16 + ka);
        const uint32_t kxA = ((kA >> 6) << 14) + (((kA & 63) << 1) ^ aX);
        const uint32_t kB  = (uint32_t)(c * 16 + kb4);
        const uint32_t kxB = ((kB >> 6) << 14) + (((kB & 63) << 1) ^ bX);

        uint32_t a0[4], a1[4], bf[4][2];
        LDSM_X4(a0, actB + aP0 + kxA);
        LDSM_X4(a1, actB + aP1 + kxA);
        #pragma unroll
        for (int np = 0; np < 2; np++) {
            uint32_t q4[4];
            LDSM_X4(q4, wB + bRow0 + ((uint32_t)np << 11) + kxB);
            bf[2*np][0]   = q4[0]; bf[2*np][1]   = q4[1];
            bf[2*np+1][0] = q4[2]; bf[2*np+1][1] = q4[3];
        }
        #pragma unroll
        for (int nt = 0; nt < 4; nt++) {
            MMA16816(acc[0][nt], a0, bf[nt]);
            MMA16816(acc[1][nt], a1, bf[nt]);
        }
    }
}

__global__ void __launch_bounds__(THREADS, 1)
mlp_fused_kernel(const float* __restrict__ x,  const float* __restrict__ W1,
                 const float* __restrict__ b1, const float* __restrict__ Wh,
                 const float* __restrict__ bh, const float* __restrict__ Wo,
                 const float* __restrict__ bo, float* __restrict__ out)
{
    extern __shared__ char smc[];
    const uint32_t smb = smem_to_u32(smc);
    const int tid = threadIdx.x;
    const int wid = tid >> 5;
    const int lane = tid & 31;
    const int o = blockIdx.x & 31;       // subnet
    const int g = blockIdx.x >> 5;       // group of 1024 rows

    const int rg = wid >> 2;             // row group (32 rows)
    const int wq = wid & 3;              // column quarter (32 cols)
    const int barid = 1 + rg;            // named barriers 1..4 (128 threads each)

    // ---- stage weights (fp16, single rounding) ----
    {
        const float* W1p = W1 + o * 64 * 128;
        for (int idx = tid; idx < 64 * 128; idx += THREADS) {
            int k = idx >> 7, j = idx & 127;         // W1[o][k][j] -> B[n=j][k]
            *reinterpret_cast<__half*>(smc + SM_W1 + swz(toff(j, k))) = __float2half_rn(W1p[idx]);
        }
        #pragma unroll
        for (int l = 0; l < 2; l++) {
            const float* Wp = Wh + ((size_t)l * 32 + o) * 128 * 128;
            const int base = l ? SM_WH1 : SM_WH0;
            for (int idx = tid; idx < 128 * 128; idx += THREADS) {
                int k = idx >> 7, j = idx & 127;
                *reinterpret_cast<__half*>(smc + base + swz(toff(j, k))) = __float2half_rn(Wp[idx]);
            }
        }
        for (int j = tid; j < 128; j += THREADS) {
            reinterpret_cast<float*>(smc + SM_BIAS)[j]       = b1[o * 128 + j];
            reinterpret_cast<float*>(smc + SM_BIAS)[128 + j] = bh[(size_t)o * 128 + j];
            reinterpret_cast<float*>(smc + SM_BIAS)[256 + j] = bh[((size_t)32 + o) * 128 + j];
            reinterpret_cast<float*>(smc + SM_WO)[j]         = Wo[o * 128 + j];
        }
    }
    __syncthreads();

    const float bo_v   = bo[o];
    const float* sbias = reinterpret_cast<const float*>(smc + SM_BIAS);
    const float* sWo   = reinterpret_cast<const float*>(smc + SM_WO);
    float* sPart       = reinterpret_cast<float*>(smc + SM_PART);

    // ---- ldmatrix lane addressing ----
    const int ra0 = rg * 32 + ((lane >> 3) & 1) * 8 + (lane & 7);
    const uint32_t aP0 = (uint32_t)(((ra0 >> 3) << 10) | ((ra0 & 7) << 7));
    const uint32_t aP1 = aP0 + (2u << 10);             // +16 rows
    const uint32_t aX  = (uint32_t)((lane & 7) << 4);
    const int ka = (lane >> 4) * 8;
    const int quad = lane >> 3;
    const int nb   = ((quad >> 1) << 3) + (lane & 7);
    const int kb4  = (quad & 1) << 3;
    const uint32_t bRow0 = (uint32_t)(((wq * 4 + (nb >> 3)) << 10) | ((nb & 7) << 7));
    const uint32_t bX    = (uint32_t)((lane & 7) << 4);

    const uint32_t act0 = smb + SM_ACT0;
    const uint32_t act1 = smb + SM_ACT1;
    const int q = lane >> 2;

    for (int t = 0; t < TILES_PER_CTA; t++) {
        const int m0 = (g * TILES_PER_CTA + t) * TILE_M;

        // ---- stage X rows for this group: [32 rows x 64 k] fp32 -> fp16 -> buf0 ----
        {
            const int p = wq * 32 + lane;             // 0..127 within group
            const int r = rg * 32 + (p >> 2);         // row
            const int kbx = (p & 3) << 4;             // k base
            const float4* xp = reinterpret_cast<const float4*>(x + (size_t)(m0 + r) * 64 + kbx);
            #pragma unroll
            for (int qq = 0; qq < 4; qq++) {
                float4 v = xp[qq];
                __half2 hh01 = __halves2half2(__float2half_rn(v.x), __float2half_rn(v.y));
                __half2 hh23 = __halves2half2(__float2half_rn(v.z), __float2half_rn(v.w));
                uint32_t off0 = swz(toff(r, kbx + 4 * qq));
                uint32_t off1 = swz(toff(r, kbx + 4 * qq + 2));
                *reinterpret_cast<uint32_t*>(smc + SM_ACT0 + off0) = *reinterpret_cast<uint32_t*>(&hh01);
                *reinterpret_cast<uint32_t*>(smc + SM_ACT0 + off1) = *reinterpret_cast<uint32_t*>(&hh23);
            }
        }
        BARG(barid);                 // (1) X visible

        // ---- layers 0 and 1: mma from src buf, epilogue to dst buf ----
        #pragma unroll
        for (int l = 0; l < 2; l++) {
            float acc[2][4][4];
            #pragma unroll
            for (int mt = 0; mt < 2; mt++)
                #pragma unroll
                for (int nt = 0; nt < 4; nt++)
                    #pragma unroll
                    for (int e = 0; e < 4; e++) acc[mt][nt][e] = 0.0f;

            const uint32_t src = (l == 0) ? act0 : act1;
            const uint32_t dstB = (l == 0) ? SM_ACT1 : SM_ACT0;
            if (l == 0)
                layer_mma<4>(acc, src, smb + SM_W1,  aP0, aP1, aX, ka, bRow0, bX, kb4);
            else
                layer_mma<8>(acc, src, smb + SM_WH0, aP0, aP1, aX, ka, bRow0, bX, kb4);

            // epilogue straight after own MMA (writes other buffer)
            const float* bias = sbias + l * 128;
            #pragma unroll
            for (int mt = 0; mt < 2; mt++) {
                const uint32_t rp0 = (uint32_t)(((rg * 4 + mt * 2) << 10) | (q << 7));
                const uint32_t rp1 = rp0 + (1u << 10);
                #pragma unroll
                for (int nt = 0; nt < 4; nt++) {
                    const int cc = wq * 32 + nt * 8 + (lane & 3) * 2;
                    const float b0v = bias[cc], b1v = bias[cc + 1];
                    float s0 = swishf(acc[mt][nt][0] + b0v);
                    float s1 = swishf(acc[mt][nt][1] + b1v);
                    float s2 = swishf(acc[mt][nt][2] + b0v);
                    float s3 = swishf(acc[mt][nt][3] + b1v);
                    __half2 hh01 = __halves2half2(__float2half_rn(s0), __float2half_rn(s1));
                    __half2 hh23 = __halves2half2(__float2half_rn(s2), __float2half_rn(s3));
                    const uint32_t kx = (uint32_t)(((cc >> 6) << 14) +
                                        (((cc & 63) << 1) ^ (q << 4)));
                    *reinterpret_cast<uint32_t*>(smc + dstB + rp0 + kx) = *reinterpret_cast<uint32_t*>(&hh01);
                    *reinterpret_cast<uint32_t*>(smc + dstB + rp1 + kx) = *reinterpret_cast<uint32_t*>(&hh23);
                }
            }
            BARG(barid);             // (2)/(3) dst visible for next layer
        }

        // ---- layer 2 + fused scalar head (reads buf0, no act writes) ----
        {
            float acc[2][4][4];
            #pragma unroll
            for (int mt = 0; mt < 2; mt++)
                #pragma unroll
                for (int nt = 0; nt < 4; nt++)
                    #pragma unroll
                    for (int e = 0; e < 4; e++) acc[mt][nt][e] = 0.0f;

            layer_mma<8>(acc, act0, smb + SM_WH1, aP0, aP1, aX, ka, bRow0, bX, kb4);

            float ps[4] = {0.f, 0.f, 0.f, 0.f};
            #pragma unroll
            for (int mt = 0; mt < 2; mt++) {
                #pragma unroll
                for (int nt = 0; nt < 4; nt++) {
                    const int cc = wq * 32 + nt * 8 + (lane & 3) * 2;
                    const float b0v = sbias[256 + cc], b1v = sbias[256 + cc + 1];
                    const float w0 = sWo[cc], w1 = sWo[cc + 1];
                    ps[mt * 2 + 0] += swishf(acc[mt][nt][0] + b0v) * w0
                                    + swishf(acc[mt][nt][1] + b1v) * w1;
                    ps[mt * 2 + 1] += swishf(acc[mt][nt][2] + b0v) * w0
                                    + swishf(acc[mt][nt][3] + b1v) * w1;
                }
            }
            #pragma unroll
            for (int i = 0; i < 4; i++) {
                ps[i] += __shfl_xor_sync(0xffffffffu, ps[i], 1);
                ps[i] += __shfl_xor_sync(0xffffffffu, ps[i], 2);
            }
            if ((lane & 3) == 0) {
                const int r = lane >> 2;              // 0..7
                float* sp = sPart + rg * 128 + wq * 32;
                sp[r]      = ps[0];
                sp[r + 8]  = ps[1];
                sp[r + 16] = ps[2];
                sp[r + 24] = ps[3];
            }
            BARG(barid);             // (4) sPart visible; also guards buf0 re-staging
            if (wq == 0) {
                const float* sp = sPart + rg * 128;
                float v = sp[lane] + sp[32 + lane] + sp[64 + lane] + sp[96 + lane];
                out[(size_t)(m0 + rg * 32 + lane) * 32 + o] = v + bo_v;
            }
        }
    }
}

extern "C" void kernel_launch(void* const* d_in, const int* in_sizes, int n_in,
                              void* d_out, int out_size) {
    const float* x  = (const float*)d_in[0];
    const float* W1 = (const float*)d_in[1];
    const float* b1 = (const float*)d_in[2];
    const float* Wh = (const float*)d_in[3];
    const float* bh = (const float*)d_in[4];
    const float* Wo = (const float*)d_in[5];
    const float* bo = (const float*)d_in[6];
    float* out = (float*)d_out;

    cudaFuncSetAttribute(mlp_fused_kernel,
                         cudaFuncAttributeMaxDynamicSharedMemorySize, SM_TOTAL);
    mlp_fused_kernel<<<GROUPS * 32, THREADS, SM_TOTAL>>>(x, W1, b1, Wh, bh, Wo, bo, out);
}

// round 11
// speedup vs baseline: 1.4553x; 1.0354x over previous
#include <cuda_runtime.h>
#include <cuda_fp16.h>
#include <cstdint>

// ============================================================
// SparseModel: 32 MLPs (64 -> 128 -> 128 -> 128 -> 1, swish)
// Dual-M-tile HMMA fp16 (B frags shared across two 128-row tiles)
// + single-MUFU swish (tanh.approx). 16 warps = 4 rg x 4 wq.
// ============================================================

#define THREADS 512
#define GROUPS 32
#define DBL_TILES 4          // 4 x 256 rows per CTA

// ---- smem layout ----
static constexpr int SM_ACT0A = 0;        // ping, tile A [128x128 fp16]
static constexpr int SM_ACT0B = 32768;    // ping, tile B
static constexpr int SM_ACT1A = 65536;    // pong, tile A
static constexpr int SM_ACT1B = 98304;    // pong, tile B
static constexpr int SM_W1    = 131072;   // W1  [128n x 64k fp16]
static constexpr int SM_WH0   = 147456;   // Wh0 [128n x 128k fp16]
static constexpr int SM_WH1   = 180224;
static constexpr int SM_PART  = 212992;          // 2 x 512 floats
static constexpr int SM_BIAS  = SM_PART + 4096;  // 3 x 128 floats
static constexpr int SM_WO    = SM_BIAS + 1536;  // 128 floats
static constexpr int SM_TOTAL = SM_WO + 512;     // 219136 <= 232448

// ---- helpers ----
__device__ __forceinline__ uint32_t smem_to_u32(const void* p) {
    uint32_t a;
    asm("{ .reg .u64 t; cvta.to.shared.u64 t, %1; cvt.u32.u64 %0, t; }" : "=r"(a) : "l"(p));
    return a;
}
__device__ __forceinline__ uint32_t swz(uint32_t b) { return b ^ ((b >> 3) & 0x70u); }
__device__ __forceinline__ uint32_t toff(int r, int k) {
    return (uint32_t)(((((k >> 6) << 4) + (r >> 3)) << 10) | ((r & 7) << 7) | ((k & 63) << 1));
}

#define LDSM_X4(r, addr) \
    asm volatile("ldmatrix.sync.aligned.m8n8.x4.shared.b16 {%0,%1,%2,%3}, [%4];" \
        : "=r"((r)[0]), "=r"((r)[1]), "=r"((r)[2]), "=r"((r)[3]) : "r"(addr))
#define MMA16816(d, a, b) \
    asm volatile("mma.sync.aligned.m16n8k16.row.col.f32.f16.f16.f32 " \
        "{%0,%1,%2,%3}, {%4,%5,%6,%7}, {%8,%9}, {%0,%1,%2,%3};" \
        : "+f"((d)[0]), "+f"((d)[1]), "+f"((d)[2]), "+f"((d)[3]) \
        : "r"((a)[0]), "r"((a)[1]), "r"((a)[2]), "r"((a)[3]), "r"((b)[0]), "r"((b)[1]))
#define BARG(id) asm volatile("bar.sync %0, 128;" :: "r"(id) : "memory")

// swish: sigmoid(v) = 0.5*tanh(0.5v)+0.5 -> swish = h*tanh(h)+h with h=v/2 (1 MUFU)
__device__ __forceinline__ float swishf(float v) {
    float t;
    const float h = 0.5f * v;
    asm("tanh.approx.f32 %0, %1;" : "=f"(t) : "f"(h));
    return fmaf(h, t, h);
}

// dual-tile layer mainloop: acc[tile][mt][nt][e]
template <int NCH>
__device__ __forceinline__ void layer_mma2(
    float acc[2][2][4][4], uint32_t srcA, uint32_t srcB, uint32_t wB,
    uint32_t aP0, uint32_t aP1, uint32_t aX, int ka,
    uint32_t bRow0, uint32_t bX, int kb4)
{
    #pragma unroll
    for (int c = 0; c < NCH; ++c) {
        const uint32_t kA  = (uint32_t)(c * 16 + ka);
        const uint32_t kxA = ((kA >> 6) << 14) + (((kA & 63) << 1) ^ aX);
        const uint32_t kB  = (uint32_t)(c * 16 + kb4);
        const uint32_t kxB = ((kB >> 6) << 14) + (((kB & 63) << 1) ^ bX);

        uint32_t bf[4][2];
        #pragma unroll
        for (int np = 0; np < 2; np++) {
            uint32_t q4[4];
            LDSM_X4(q4, wB + bRow0 + ((uint32_t)np << 11) + kxB);
            bf[2*np][0]   = q4[0]; bf[2*np][1]   = q4[1];
            bf[2*np+1][0] = q4[2]; bf[2*np+1][1] = q4[3];
        }
        uint32_t a0A[4], a1A[4], a0B[4], a1B[4];
        LDSM_X4(a0A, srcA + aP0 + kxA);
        LDSM_X4(a1A, srcA + aP1 + kxA);
        LDSM_X4(a0B, srcB + aP0 + kxA);
        LDSM_X4(a1B, srcB + aP1 + kxA);

        #pragma unroll
        for (int nt = 0; nt < 4; nt++) {
            MMA16816(acc[0][0][nt], a0A, bf[nt]);
            MMA16816(acc[0][1][nt], a1A, bf[nt]);
            MMA16816(acc[1][0][nt], a0B, bf[nt]);
            MMA16816(acc[1][1][nt], a1B, bf[nt]);
        }
    }
}

__global__ void __launch_bounds__(THREADS, 1)
mlp_fused_kernel(const float* __restrict__ x,  const float* __restrict__ W1,
                 const float* __restrict__ b1, const float* __restrict__ Wh,
                 const float* __restrict__ bh, const float* __restrict__ Wo,
                 const float* __restrict__ bo, float* __restrict__ out)
{
    extern __shared__ char smc[];
    const uint32_t smb = smem_to_u32(smc);
    const int tid = threadIdx.x;
    const int wid = tid >> 5;
    const int lane = tid & 31;
    const int o = blockIdx.x & 31;       // subnet
    const int g = blockIdx.x >> 5;       // group of 1024 rows

    const int rg = wid >> 2;             // row group (32 rows)
    const int wq = wid & 3;              // column quarter (32 cols)
    const int barid = 1 + rg;            // named barriers 1..4 (128 threads each)

    // ---- stage weights (fp16, single rounding) ----
    {
        const float* W1p = W1 + o * 64 * 128;
        for (int idx = tid; idx < 64 * 128; idx += THREADS) {
            int k = idx >> 7, j = idx & 127;         // W1[o][k][j] -> B[n=j][k]
            *reinterpret_cast<__half*>(smc + SM_W1 + swz(toff(j, k))) = __float2half_rn(W1p[idx]);
        }
        #pragma unroll
        for (int l = 0; l < 2; l++) {
            const float* Wp = Wh + ((size_t)l * 32 + o) * 128 * 128;
            const int base = l ? SM_WH1 : SM_WH0;
            for (int idx = tid; idx < 128 * 128; idx += THREADS) {
                int k = idx >> 7, j = idx & 127;
                *reinterpret_cast<__half*>(smc + base + swz(toff(j, k))) = __float2half_rn(Wp[idx]);
            }
        }
        for (int j = tid; j < 128; j += THREADS) {
            reinterpret_cast<float*>(smc + SM_BIAS)[j]       = b1[o * 128 + j];
            reinterpret_cast<float*>(smc + SM_BIAS)[128 + j] = bh[(size_t)o * 128 + j];
            reinterpret_cast<float*>(smc + SM_BIAS)[256 + j] = bh[((size_t)32 + o) * 128 + j];
            reinterpret_cast<float*>(smc + SM_WO)[j]         = Wo[o * 128 + j];
        }
    }
    __syncthreads();

    const float bo_v   = bo[o];
    const float* sbias = reinterpret_cast<const float*>(smc + SM_BIAS);
    const float* sWo   = reinterpret_cast<const float*>(smc + SM_WO);
    float* sPart       = reinterpret_cast<float*>(smc + SM_PART);

    // ---- ldmatrix lane addressing ----
    const int ra0 = rg * 32 + ((lane >> 3) & 1) * 8 + (lane & 7);
    const uint32_t aP0 = (uint32_t)(((ra0 >> 3) << 10) | ((ra0 & 7) << 7));
    const uint32_t aP1 = aP0 + (2u << 10);             // +16 rows
    const uint32_t aX  = (uint32_t)((lane & 7) << 4);
    const int ka = (lane >> 4) * 8;
    const int quad = lane >> 3;
    const int nb   = ((quad >> 1) << 3) + (lane & 7);
    const int kb4  = (quad & 1) << 3;
    const uint32_t bRow0 = (uint32_t)(((wq * 4 + (nb >> 3)) << 10) | ((nb & 7) << 7));
    const uint32_t bX    = (uint32_t)((lane & 7) << 4);

    const int q = lane >> 2;

    for (int t = 0; t < DBL_TILES; t++) {
        const int m0 = (g * DBL_TILES + t) * 256;

        // ---- stage X rows for both tiles: [32 rows x 64 k] fp32 -> fp16 -> ping ----
        {
            const int p = wq * 32 + lane;             // 0..127 within group
            const int r = rg * 32 + (p >> 2);
            const int kbx = (p & 3) << 4;
            #pragma unroll
            for (int tt = 0; tt < 2; tt++) {
                const float4* xp = reinterpret_cast<const float4*>(
                    x + (size_t)(m0 + tt * 128 + r) * 64 + kbx);
                const int dst = tt ? SM_ACT0B : SM_ACT0A;
                #pragma unroll
                for (int qq = 0; qq < 4; qq++) {
                    float4 v = xp[qq];
                    __half2 hh01 = __halves2half2(__float2half_rn(v.x), __float2half_rn(v.y));
                    __half2 hh23 = __halves2half2(__float2half_rn(v.z), __float2half_rn(v.w));
                    uint32_t off0 = swz(toff(r, kbx + 4 * qq));
                    uint32_t off1 = swz(toff(r, kbx + 4 * qq + 2));
                    *reinterpret_cast<uint32_t*>(smc + dst + off0) = *reinterpret_cast<uint32_t*>(&hh01);
                    *reinterpret_cast<uint32_t*>(smc + dst + off1) = *reinterpret_cast<uint32_t*>(&hh23);
                }
            }
        }
        BARG(barid);                 // (1) X visible

        // ---- layers 0 and 1 ----
        #pragma unroll
        for (int l = 0; l < 2; l++) {
            float acc[2][2][4][4];
            #pragma unroll
            for (int tt = 0; tt < 2; tt++)
                #pragma unroll
                for (int mt = 0; mt < 2; mt++)
                    #pragma unroll
                    for (int nt = 0; nt < 4; nt++)
                        #pragma unroll
                        for (int e = 0; e < 4; e++) acc[tt][mt][nt][e] = 0.0f;

            const uint32_t srcA = smb + ((l == 0) ? SM_ACT0A : SM_ACT1A);
            const uint32_t srcB = smb + ((l == 0) ? SM_ACT0B : SM_ACT1B);
            const int dstA = (l == 0) ? SM_ACT1A : SM_ACT0A;
            const int dstB = (l == 0) ? SM_ACT1B : SM_ACT0B;
            if (l == 0)
                layer_mma2<4>(acc, srcA, srcB, smb + SM_W1,  aP0, aP1, aX, ka, bRow0, bX, kb4);
            else
                layer_mma2<8>(acc, srcA, srcB, smb + SM_WH0, aP0, aP1, aX, ka, bRow0, bX, kb4);

            const float* bias = sbias + l * 128;
            #pragma unroll
            for (int tt = 0; tt < 2; tt++) {
                const int dst = tt ? dstB : dstA;
                #pragma unroll
                for (int mt = 0; mt < 2; mt++) {
                    const uint32_t rp0 = (uint32_t)(((rg * 4 + mt * 2) << 10) | (q << 7));
                    const uint32_t rp1 = rp0 + (1u << 10);
                    #pragma unroll
                    for (int nt = 0; nt < 4; nt++) {
                        const int cc = wq * 32 + nt * 8 + (lane & 3) * 2;
                        const float b0v = bias[cc], b1v = bias[cc + 1];
                        float s0 = swishf(acc[tt][mt][nt][0] + b0v);
                        float s1 = swishf(acc[tt][mt][nt][1] + b1v);
                        float s2 = swishf(acc[tt][mt][nt][2] + b0v);
                        float s3 = swishf(acc[tt][mt][nt][3] + b1v);
                        __half2 hh01 = __halves2half2(__float2half_rn(s0), __float2half_rn(s1));
                        __half2 hh23 = __halves2half2(__float2half_rn(s2), __float2half_rn(s3));
                        const uint32_t kx = (uint32_t)(((cc >> 6) << 14) +
                                            (((cc & 63) << 1) ^ (q << 4)));
                        *reinterpret_cast<uint32_t*>(smc + dst + rp0 + kx) = *reinterpret_cast<uint32_t*>(&hh01);
                        *reinterpret_cast<uint32_t*>(smc + dst + rp1 + kx) = *reinterpret_cast<uint32_t*>(&hh23);
                    }
                }
            }
            BARG(barid);             // (2)/(3) dst visible for next layer
        }

        // ---- layer 2 + fused scalar head (reads ping, no act writes) ----
        {
            float acc[2][2][4][4];
            #pragma unroll
            for (int tt = 0; tt < 2; tt++)
                #pragma unroll
                for (int mt = 0; mt < 2; mt++)
                    #pragma unroll
                    for (int nt = 0; nt < 4; nt++)
                        #pragma unroll
                        for (int e = 0; e < 4; e++) acc[tt][mt][nt][e] = 0.0f;

            layer_mma2<8>(acc, smb + SM_ACT0A, smb + SM_ACT0B, smb + SM_WH1,
                          aP0, aP1, aX, ka, bRow0, bX, kb4);

            #pragma unroll
            for (int tt = 0; tt < 2; tt++) {
                float ps[4] = {0.f, 0.f, 0.f, 0.f};
                #pragma unroll
                for (int mt = 0; mt < 2; mt++) {
                    #pragma unroll
                    for (int nt = 0; nt < 4; nt++) {
                        const int cc = wq * 32 + nt * 8 + (lane & 3) * 2;
                        const float b0v = sbias[256 + cc], b1v = sbias[256 + cc + 1];
                        const float w0 = sWo[cc], w1 = sWo[cc + 1];
                        ps[mt * 2 + 0] += swishf(acc[tt][mt][nt][0] + b0v) * w0
                                        + swishf(acc[tt][mt][nt][1] + b1v) * w1;
                        ps[mt * 2 + 1] += swishf(acc[tt][mt][nt][2] + b0v) * w0
                                        + swishf(acc[tt][mt][nt][3] + b1v) * w1;
                    }
                }
                #pragma unroll
                for (int i = 0; i < 4; i++) {
                    ps[i] += __shfl_xor_sync(0xffffffffu, ps[i], 1);
                    ps[i] += __shfl_xor_sync(0xffffffffu, ps[i], 2);
                }
                if ((lane & 3) == 0) {
                    const int r = lane >> 2;
                    float* sp = sPart + tt * 512 + rg * 128 + wq * 32;
                    sp[r]      = ps[0];
                    sp[r + 8]  = ps[1];
                    sp[r + 16] = ps[2];
                    sp[r + 24] = ps[3];
                }
            }
            BARG(barid);             // (4) sPart visible; also guards ping re-staging
            if (wq == 0) {
                #pragma unroll
                for (int tt = 0; tt < 2; tt++) {
                    const float* sp = sPart + tt * 512 + rg * 128;
                    float v = sp[lane] + sp[32 + lane] + sp[64 + lane] + sp[96 + lane];
                    out[(size_t)(m0 + tt * 128 + rg * 32 + lane) * 32 + o] = v + bo_v;
                }
            }
        }
    }
}

extern "C" void kernel_launch(void* const* d_in, const int* in_sizes, int n_in,
                              void* d_out, int out_size) {
    const float* x  = (const float*)d_in[0];
    const float* W1 = (const float*)d_in[1];
    const float* b1 = (const float*)d_in[2];
    const float* Wh = (const float*)d_in[3];
    const float* bh = (const float*)d_in[4];
    const float* Wo = (const float*)d_in[5];
    const float* bo = (const float*)d_in[6];
    float* out = (float*)d_out;

    cudaFuncSetAttribute(mlp_fused_kernel,
                         cudaFuncAttributeMaxDynamicSharedMemorySize, SM_TOTAL);
    mlp_fused_kernel<<<GROUPS * 32, THREADS, SM_TOTAL>>>(x, W1, b1, Wh, bh, Wo, bo, out);
}